// round 12
// baseline (speedup 1.0000x reference)
#include <cuda_runtime.h>
#include <math.h>

// Problem dims
#define B_   256
#define T1_  128
#define S_   128
#define A_   32
#define H_   1024
#define E_   1024

// Output layout (floats), tuple order: b1, s_p, mu_p, std_p, s_q, mu_q, std_q
#define O_B_SZ   (B_ * T1_ * H_)          // 33,554,432
#define O_S_SZ   (B_ * T1_ * S_)          // 4,194,304
#define SSTRIDE  (T1_ * S_)               // 16384 (row stride of (B,T1,S) slices)
#define BSTRIDE  (T1_ * H_)               // 131072

// ---------------- scratch (static device memory; no allocations) ------------
__device__ float g_OB [B_ * T1_ * H_];    // precomputed o @ W_bpos_o^T + b_bpos  (134 MB)
__device__ float g_x  [B_ * H_];          // x = relu([s,a] @ W_sa^T + b_sa)
__device__ float g_G  [B_ * 6 * H_];      // [gi (3H) | gh (3H)]
__device__ float g_HPQ[B_ * 2 * H_];      // [hp (H) | hq (H)]

// ---------------- 64x64 fp32 GEMM core: 64 threads, 8x8 per thread ----------
// smem layout: [k][m] / [k][n], row stride 68 floats (16B-aligned, conflict-light)
__device__ __forceinline__ void mma_tile(const float (&As)[16][68],
                                         const float (&Bs)[16][68],
                                         int tr, int tc, float (&acc)[8][8])
{
#pragma unroll
    for (int k = 0; k < 16; k++) {
        float4 a0 = *reinterpret_cast<const float4*>(&As[k][tr * 8]);
        float4 a1 = *reinterpret_cast<const float4*>(&As[k][tr * 8 + 4]);
        float4 b0 = *reinterpret_cast<const float4*>(&Bs[k][tc * 8]);
        float4 b1 = *reinterpret_cast<const float4*>(&Bs[k][tc * 8 + 4]);
        float av[8] = {a0.x, a0.y, a0.z, a0.w, a1.x, a1.y, a1.z, a1.w};
        float bv[8] = {b0.x, b0.y, b0.z, b0.w, b1.x, b1.y, b1.z, b1.w};
#pragma unroll
        for (int i = 0; i < 8; i++)
#pragma unroll
            for (int j = 0; j < 8; j++)
                acc[i][j] = fmaf(av[i], bv[j], acc[i][j]);
    }
}

// ---------------- precompute: OB = Obs @ W_bpos[:,1024:2048]^T + b_bpos ------
// M = B*T1 = 32768, N = 1024, K = 1024.  grid (16, 512), 64 threads.
__global__ void __launch_bounds__(64)
ob_gemm(const float* __restrict__ Obs, const float* __restrict__ W_bpos,
        const float* __restrict__ b_bpos)
{
    __shared__ __align__(16) float As[16][68];
    __shared__ __align__(16) float Bs[16][68];
    const int tid = threadIdx.x;
    const int lk = tid & 15, lr = tid >> 4;     // load: k, row-group
    const int tc = tid & 7,  tr = tid >> 3;     // compute: col-group, row-group
    const int n0 = blockIdx.x * 64;
    const int m0 = blockIdx.y * 64;
    float acc[8][8] = {};
    for (int k0 = 0; k0 < 1024; k0 += 16) {
#pragma unroll
        for (int i = 0; i < 16; i++) {
            int r = lr + i * 4;
            As[lk][r] = Obs[(size_t)(m0 + r) * 1024 + k0 + lk];
            Bs[lk][r] = W_bpos[(size_t)(n0 + r) * 2048 + 1024 + k0 + lk];
        }
        __syncthreads();
        mma_tile(As, Bs, tr, tc, acc);
        __syncthreads();
    }
#pragma unroll
    for (int i = 0; i < 8; i++) {
        int m = m0 + tr * 8 + i;
#pragma unroll
        for (int j = 0; j < 8; j++) {
            int n = n0 + tc * 8 + j;
            g_OB[(size_t)m * 1024 + n] = acc[i][j] + b_bpos[n];
        }
    }
}

// ---------------- K1: x = relu([s,a] @ W_sa^T + b_sa) ------------------------
// M=256, N=1024, K=160.  grid (16, 4), 64 threads.
__global__ void __launch_bounds__(64)
k1_x(const float* __restrict__ s, int ss,
     const float* __restrict__ a, int sa,
     const float* __restrict__ W_sa, const float* __restrict__ b_sa)
{
    __shared__ __align__(16) float As[16][68];
    __shared__ __align__(16) float Bs[16][68];
    const int tid = threadIdx.x;
    const int lk = tid & 15, lr = tid >> 4;
    const int tc = tid & 7,  tr = tid >> 3;
    const int n0 = blockIdx.x * 64;
    const int m0 = blockIdx.y * 64;
    float acc[8][8] = {};
    for (int k0 = 0; k0 < 160; k0 += 16) {
        int kk = k0 + lk;
#pragma unroll
        for (int i = 0; i < 16; i++) {
            int r = lr + i * 4;
            As[lk][r] = (kk < 128) ? s[(size_t)(m0 + r) * ss + kk]
                                   : a[(size_t)(m0 + r) * sa + (kk - 128)];
            Bs[lk][r] = W_sa[(n0 + r) * 160 + kk];
        }
        __syncthreads();
        mma_tile(As, Bs, tr, tc, acc);
        __syncthreads();
    }
#pragma unroll
    for (int i = 0; i < 8; i++) {
        int m = m0 + tr * 8 + i;
#pragma unroll
        for (int j = 0; j < 8; j++) {
            int n = n0 + tc * 8 + j;
            g_x[m * 1024 + n] = fmaxf(acc[i][j] + b_sa[n], 0.0f);
        }
    }
}

// ---------------- K2: G = [x @ W_ih^T + b_ih | bprev @ W_hh^T + b_hh] -------
// Column space 6144; cols < 3072 use A=x, else A=bprev.  grid (96, 4).
__global__ void __launch_bounds__(64)
k2_gemm(const float* __restrict__ bprev, int bs,
        const float* __restrict__ W_ih, const float* __restrict__ W_hh,
        const float* __restrict__ b_ih, const float* __restrict__ b_hh)
{
    __shared__ __align__(16) float As[16][68];
    __shared__ __align__(16) float Bs[16][68];
    const int tid = threadIdx.x;
    const int lk = tid & 15, lr = tid >> 4;
    const int tc = tid & 7,  tr = tid >> 3;
    const int n0 = blockIdx.x * 64;
    const int m0 = blockIdx.y * 64;
    const bool isX = (n0 < 3072);
    const float* W    = isX ? W_ih : W_hh;
    const float* bias = isX ? b_ih : b_hh;
    const int wn0 = isX ? n0 : (n0 - 3072);
    float acc[8][8] = {};
    for (int k0 = 0; k0 < 1024; k0 += 16) {
#pragma unroll
        for (int i = 0; i < 16; i++) {
            int r = lr + i * 4;
            As[lk][r] = isX ? g_x[(m0 + r) * 1024 + k0 + lk]
                            : bprev[(size_t)(m0 + r) * bs + k0 + lk];
            Bs[lk][r] = W[(size_t)(wn0 + r) * 1024 + k0 + lk];
        }
        __syncthreads();
        mma_tile(As, Bs, tr, tc, acc);
        __syncthreads();
    }
#pragma unroll
    for (int i = 0; i < 8; i++) {
        int m = m0 + tr * 8 + i;
#pragma unroll
        for (int j = 0; j < 8; j++) {
            int n = n0 + tc * 8 + j;
            g_G[(size_t)m * 6144 + n] = acc[i][j] + bias[wn0 + tc * 8 + j];
        }
    }
}

// ---------------- K2b: fused GRU gates -> b1 = Beliefs[:,t,:] ---------------
__global__ void k2_gates(const float* __restrict__ bprev, int bs,
                         float* __restrict__ bout /* Beliefs + t*H, stride BSTRIDE */)
{
    int idx = blockIdx.x * 256 + threadIdx.x;   // < 256*1024
    int m = idx >> 10, n = idx & 1023;
    const float* g = g_G + (size_t)m * 6144;
    float ir = g[n],          iz = g[n + 1024],        in_ = g[n + 2048];
    float hr = g[3072 + n],   hz = g[3072 + 1024 + n], hn  = g[3072 + 2048 + n];
    float r  = 1.0f / (1.0f + expf(-(ir + hr)));
    float z  = 1.0f / (1.0f + expf(-(iz + hz)));
    float nn = tanhf(in_ + r * hn);
    float h  = bprev[(size_t)m * bs + n];
    bout[(size_t)m * BSTRIDE + n] = (1.0f - z) * nn + z * h;
}

// ---------------- K3: HPQ = [relu(b1@W_bpri^T+b_bpri) | relu(b1@W_bpos_b^T+OB)]
// N = 2048, K = 1024, A = Beliefs slice (lda = BSTRIDE).  grid (32, 4).
__global__ void __launch_bounds__(64)
k3_gemm(const float* __restrict__ b1, const float* __restrict__ W_bpri,
        const float* __restrict__ b_bpri, const float* __restrict__ W_bpos, int t)
{
    __shared__ __align__(16) float As[16][68];
    __shared__ __align__(16) float Bs[16][68];
    const int tid = threadIdx.x;
    const int lk = tid & 15, lr = tid >> 4;
    const int tc = tid & 7,  tr = tid >> 3;
    const int n0 = blockIdx.x * 64;
    const int m0 = blockIdx.y * 64;
    const bool pri = (n0 < 1024);
    float acc[8][8] = {};
    for (int k0 = 0; k0 < 1024; k0 += 16) {
#pragma unroll
        for (int i = 0; i < 16; i++) {
            int r = lr + i * 4;
            As[lk][r] = b1[(size_t)(m0 + r) * BSTRIDE + k0 + lk];
            Bs[lk][r] = pri ? W_bpri[(size_t)(n0 + r) * 1024 + k0 + lk]
                            : W_bpos[(size_t)(n0 + r - 1024) * 2048 + k0 + lk];
        }
        __syncthreads();
        mma_tile(As, Bs, tr, tc, acc);
        __syncthreads();
    }
#pragma unroll
    for (int i = 0; i < 8; i++) {
        int m = m0 + tr * 8 + i;
#pragma unroll
        for (int j = 0; j < 8; j++) {
            int n = n0 + tc * 8 + j;
            float add = pri ? b_bpri[n]
                            : g_OB[((size_t)m * T1_ + t) * 1024 + (n - 1024)];
            g_HPQ[(size_t)m * 2048 + n] = fmaxf(acc[i][j] + add, 0.0f);
        }
    }
}

// ---------------- K4: heads. Col space 512 = [prior 256 | posterior 256],
// interleaved pairs: col 2p = mu_p, col 2p+1 = h2_p.  grid (8, 4).
__global__ void __launch_bounds__(64)
k4_heads(const float* __restrict__ W_spri, const float* __restrict__ b_spri,
         const float* __restrict__ W_spos, const float* __restrict__ b_spos,
         const float* __restrict__ np, const float* __restrict__ nq,
         float* __restrict__ o_sp, float* __restrict__ o_mup, float* __restrict__ o_stp,
         float* __restrict__ o_sq, float* __restrict__ o_muq, float* __restrict__ o_stq)
{
    __shared__ __align__(16) float As[16][68];
    __shared__ __align__(16) float Bs[16][68];
    const int tid = threadIdx.x;
    const int lk = tid & 15, lr = tid >> 4;
    const int tc = tid & 7,  tr = tid >> 3;
    const int n0 = blockIdx.x * 64;               // 0..511
    const int m0 = blockIdx.y * 64;
    const int side = n0 >> 8;                      // 0 = prior, 1 = posterior
    const float* W    = side ? W_spos : W_spri;
    const float* bias = side ? b_spos : b_spri;
    const float* nz   = side ? nq : np;
    float* o_s  = side ? o_sq  : o_sp;
    float* o_mu = side ? o_muq : o_mup;
    float* o_st = side ? o_stq : o_stp;
    float acc[8][8] = {};
    for (int k0 = 0; k0 < 1024; k0 += 16) {
#pragma unroll
        for (int i = 0; i < 16; i++) {
            int r = lr + i * 4;
            As[lk][r] = g_HPQ[(m0 + r) * 2048 + side * 1024 + k0 + lk];
            int cc  = (n0 + r) & 255;              // within-side column
            int row = (cc >> 1) + (cc & 1) * 128;  // mu rows [0,128), h2 rows [128,256)
            Bs[lk][r] = W[row * 1024 + k0 + lk];
        }
        __syncthreads();
        mma_tile(As, Bs, tr, tc, acc);
        __syncthreads();
    }
#pragma unroll
    for (int i = 0; i < 8; i++) {
        int m = m0 + tr * 8 + i;
#pragma unroll
        for (int j = 0; j < 8; j += 2) {
            int cc = (n0 + tc * 8 + j) & 255;
            int p  = cc >> 1;
            float mu = acc[i][j]     + bias[p];
            float h2 = acc[i][j + 1] + bias[p + 128];
            float sd = ((h2 > 20.0f) ? h2 : log1pf(expf(h2))) + 0.1f;  // softplus + MIN_STD
            float ep = nz[(size_t)m * SSTRIDE + p];
            size_t o = (size_t)m * SSTRIDE + p;
            o_mu[o] = mu;
            o_st[o] = sd;
            o_s [o] = mu + sd * ep;
        }
    }
}

// ---------------- host: capture-safe launch sequence -------------------------
extern "C" void kernel_launch(void* const* d_in, const int* in_sizes, int n_in,
                              void* d_out, int out_size)
{
    (void)in_sizes; (void)n_in; (void)out_size;
    const float* s0     = (const float*)d_in[0];
    const float* b0     = (const float*)d_in[1];
    const float* Act    = (const float*)d_in[2];
    const float* Obs    = (const float*)d_in[3];
    const float* np     = (const float*)d_in[4];
    const float* nq     = (const float*)d_in[5];
    const float* W_sa   = (const float*)d_in[6];
    const float* b_sa   = (const float*)d_in[7];
    const float* W_ih   = (const float*)d_in[8];
    const float* W_hh   = (const float*)d_in[9];
    const float* b_ih   = (const float*)d_in[10];
    const float* b_hh   = (const float*)d_in[11];
    const float* W_bpri = (const float*)d_in[12];
    const float* b_bpri = (const float*)d_in[13];
    const float* W_spri = (const float*)d_in[14];
    const float* b_spri = (const float*)d_in[15];
    const float* W_bpos = (const float*)d_in[16];
    const float* b_bpos = (const float*)d_in[17];
    const float* W_spos = (const float*)d_in[18];
    const float* b_spos = (const float*)d_in[19];

    float* out   = (float*)d_out;
    float* O_b   = out;                    // (B,T1,H)
    float* O_sp  = O_b   + O_B_SZ;         // (B,T1,S) x6
    float* O_mup = O_sp  + O_S_SZ;
    float* O_stp = O_mup + O_S_SZ;
    float* O_sq  = O_stp + O_S_SZ;
    float* O_muq = O_sq  + O_S_SZ;
    float* O_stq = O_muq + O_S_SZ;

    // Hoisted observation projection (independent of recurrence)
    ob_gemm<<<dim3(16, 512), 64>>>(Obs, W_bpos, b_bpos);

    for (int t = 0; t < T1_; t++) {
        const float* sprev = t ? (O_sq + (size_t)(t - 1) * S_) : s0;
        const int    ss    = t ? SSTRIDE : S_;
        const float* bprev = t ? (O_b + (size_t)(t - 1) * H_) : b0;
        const int    bs    = t ? BSTRIDE : H_;

        k1_x   <<<dim3(16, 4), 64>>>(sprev, ss, Act + (size_t)t * A_, T1_ * A_, W_sa, b_sa);
        k2_gemm<<<dim3(96, 4), 64>>>(bprev, bs, W_ih, W_hh, b_ih, b_hh);
        k2_gates<<<1024, 256>>>(bprev, bs, O_b + (size_t)t * H_);
        k3_gemm<<<dim3(32, 4), 64>>>(O_b + (size_t)t * H_, W_bpri, b_bpri, W_bpos, t);
        k4_heads<<<dim3(8, 4), 64>>>(W_spri, b_spri, W_spos, b_spos,
                                     np + (size_t)t * S_, nq + (size_t)t * S_,
                                     O_sp  + (size_t)t * S_, O_mup + (size_t)t * S_,
                                     O_stp + (size_t)t * S_, O_sq  + (size_t)t * S_,
                                     O_muq + (size_t)t * S_, O_stq + (size_t)t * S_);
    }
}

// round 13
// speedup vs baseline: 1.0083x; 1.0083x over previous
#include <cuda_runtime.h>
#include <math.h>

// Problem dims
#define B_   256
#define T1_  128
#define S_   128
#define A_   32
#define H_   1024
#define E_   1024

// Output layout (floats), tuple order: b1, s_p, mu_p, std_p, s_q, mu_q, std_q
#define O_B_SZ   (B_ * T1_ * H_)          // 33,554,432
#define O_S_SZ   (B_ * T1_ * S_)          // 4,194,304
#define SSTRIDE  (T1_ * S_)               // 16384 (row stride of (B,T1,S) slices)
#define BSTRIDE  (T1_ * H_)               // 131072

// ---------------- scratch (static device memory; no allocations) ------------
__device__ float g_OB [B_ * T1_ * H_];    // precomputed o @ W_bpos_o^T + b_bpos  (134 MB)
__device__ float g_x  [B_ * H_];          // x = relu([s,a] @ W_sa^T + b_sa)
__device__ float g_G  [B_ * 6 * H_];      // [gi (3H) | gh (3H)]
__device__ float g_HPQ[B_ * 2 * H_];      // [hp (H) | hq (H)]

// ---------------- 64x64 fp32 GEMM core: 64 threads, 8x8 per thread ----------
// smem layout: [k][m] / [k][n], row stride 68 floats (16B-aligned, conflict-light)
__device__ __forceinline__ void mma_tile(const float (&As)[16][68],
                                         const float (&Bs)[16][68],
                                         int tr, int tc, float (&acc)[8][8])
{
#pragma unroll
    for (int k = 0; k < 16; k++) {
        float4 a0 = *reinterpret_cast<const float4*>(&As[k][tr * 8]);
        float4 a1 = *reinterpret_cast<const float4*>(&As[k][tr * 8 + 4]);
        float4 b0 = *reinterpret_cast<const float4*>(&Bs[k][tc * 8]);
        float4 b1 = *reinterpret_cast<const float4*>(&Bs[k][tc * 8 + 4]);
        float av[8] = {a0.x, a0.y, a0.z, a0.w, a1.x, a1.y, a1.z, a1.w};
        float bv[8] = {b0.x, b0.y, b0.z, b0.w, b1.x, b1.y, b1.z, b1.w};
#pragma unroll
        for (int i = 0; i < 8; i++)
#pragma unroll
            for (int j = 0; j < 8; j++)
                acc[i][j] = fmaf(av[i], bv[j], acc[i][j]);
    }
}

// ---------------- precompute: OB = Obs @ W_bpos[:,1024:2048]^T + b_bpos ------
// M = B*T1 = 32768, N = 1024, K = 1024.  grid (16, 512), 64 threads.
__global__ void __launch_bounds__(64)
ob_gemm(const float* __restrict__ Obs, const float* __restrict__ W_bpos,
        const float* __restrict__ b_bpos)
{
    __shared__ __align__(16) float As[16][68];
    __shared__ __align__(16) float Bs[16][68];
    const int tid = threadIdx.x;
    const int lk = tid & 15, lr = tid >> 4;     // load: k, row-group
    const int tc = tid & 7,  tr = tid >> 3;     // compute: col-group, row-group
    const int n0 = blockIdx.x * 64;
    const int m0 = blockIdx.y * 64;
    float acc[8][8] = {};
    for (int k0 = 0; k0 < 1024; k0 += 16) {
#pragma unroll
        for (int i = 0; i < 16; i++) {
            int r = lr + i * 4;
            As[lk][r] = Obs[(size_t)(m0 + r) * 1024 + k0 + lk];
            Bs[lk][r] = W_bpos[(size_t)(n0 + r) * 2048 + 1024 + k0 + lk];
        }
        __syncthreads();
        mma_tile(As, Bs, tr, tc, acc);
        __syncthreads();
    }
#pragma unroll
    for (int i = 0; i < 8; i++) {
        int m = m0 + tr * 8 + i;
#pragma unroll
        for (int j = 0; j < 8; j++) {
            int n = n0 + tc * 8 + j;
            g_OB[(size_t)m * 1024 + n] = acc[i][j] + b_bpos[n];
        }
    }
}

// ---------------- K1: x = relu([s,a] @ W_sa^T + b_sa) ------------------------
// M=256, N=1024, K=160.  grid (16, 4), 64 threads.
__global__ void __launch_bounds__(64)
k1_x(const float* __restrict__ s, int ss,
     const float* __restrict__ a, int sa,
     const float* __restrict__ W_sa, const float* __restrict__ b_sa)
{
    __shared__ __align__(16) float As[16][68];
    __shared__ __align__(16) float Bs[16][68];
    const int tid = threadIdx.x;
    const int lk = tid & 15, lr = tid >> 4;
    const int tc = tid & 7,  tr = tid >> 3;
    const int n0 = blockIdx.x * 64;
    const int m0 = blockIdx.y * 64;
    float acc[8][8] = {};
    for (int k0 = 0; k0 < 160; k0 += 16) {
        int kk = k0 + lk;
#pragma unroll
        for (int i = 0; i < 16; i++) {
            int r = lr + i * 4;
            As[lk][r] = (kk < 128) ? s[(size_t)(m0 + r) * ss + kk]
                                   : a[(size_t)(m0 + r) * sa + (kk - 128)];
            Bs[lk][r] = W_sa[(n0 + r) * 160 + kk];
        }
        __syncthreads();
        mma_tile(As, Bs, tr, tc, acc);
        __syncthreads();
    }
#pragma unroll
    for (int i = 0; i < 8; i++) {
        int m = m0 + tr * 8 + i;
#pragma unroll
        for (int j = 0; j < 8; j++) {
            int n = n0 + tc * 8 + j;
            g_x[m * 1024 + n] = fmaxf(acc[i][j] + b_sa[n], 0.0f);
        }
    }
}

// ---------------- K2: G = [x @ W_ih^T + b_ih | bprev @ W_hh^T + b_hh] -------
// Column space 6144; cols < 3072 use A=x, else A=bprev.  grid (96, 4).
__global__ void __launch_bounds__(64)
k2_gemm(const float* __restrict__ bprev, int bs,
        const float* __restrict__ W_ih, const float* __restrict__ W_hh,
        const float* __restrict__ b_ih, const float* __restrict__ b_hh)
{
    __shared__ __align__(16) float As[16][68];
    __shared__ __align__(16) float Bs[16][68];
    const int tid = threadIdx.x;
    const int lk = tid & 15, lr = tid >> 4;
    const int tc = tid & 7,  tr = tid >> 3;
    const int n0 = blockIdx.x * 64;
    const int m0 = blockIdx.y * 64;
    const bool isX = (n0 < 3072);
    const float* W    = isX ? W_ih : W_hh;
    const float* bias = isX ? b_ih : b_hh;
    const int wn0 = isX ? n0 : (n0 - 3072);
    float acc[8][8] = {};
    for (int k0 = 0; k0 < 1024; k0 += 16) {
#pragma unroll
        for (int i = 0; i < 16; i++) {
            int r = lr + i * 4;
            As[lk][r] = isX ? g_x[(m0 + r) * 1024 + k0 + lk]
                            : bprev[(size_t)(m0 + r) * bs + k0 + lk];
            Bs[lk][r] = W[(size_t)(wn0 + r) * 1024 + k0 + lk];
        }
        __syncthreads();
        mma_tile(As, Bs, tr, tc, acc);
        __syncthreads();
    }
#pragma unroll
    for (int i = 0; i < 8; i++) {
        int m = m0 + tr * 8 + i;
#pragma unroll
        for (int j = 0; j < 8; j++) {
            int n = n0 + tc * 8 + j;
            g_G[(size_t)m * 6144 + n] = acc[i][j] + bias[wn0 + tc * 8 + j];
        }
    }
}

// ---------------- K2b: fused GRU gates -> b1 = Beliefs[:,t,:] ---------------
__global__ void k2_gates(const float* __restrict__ bprev, int bs,
                         float* __restrict__ bout /* Beliefs + t*H, stride BSTRIDE */)
{
    int idx = blockIdx.x * 256 + threadIdx.x;   // < 256*1024
    int m = idx >> 10, n = idx & 1023;
    const float* g = g_G + (size_t)m * 6144;
    float ir = g[n],          iz = g[n + 1024],        in_ = g[n + 2048];
    float hr = g[3072 + n],   hz = g[3072 + 1024 + n], hn  = g[3072 + 2048 + n];
    float r  = 1.0f / (1.0f + expf(-(ir + hr)));
    float z  = 1.0f / (1.0f + expf(-(iz + hz)));
    float nn = tanhf(in_ + r * hn);
    float h  = bprev[(size_t)m * bs + n];
    bout[(size_t)m * BSTRIDE + n] = (1.0f - z) * nn + z * h;
}

// ---------------- K3: HPQ = [relu(b1@W_bpri^T+b_bpri) | relu(b1@W_bpos_b^T+OB)]
// N = 2048, K = 1024, A = Beliefs slice (lda = BSTRIDE).  grid (32, 4).
__global__ void __launch_bounds__(64)
k3_gemm(const float* __restrict__ b1, const float* __restrict__ W_bpri,
        const float* __restrict__ b_bpri, const float* __restrict__ W_bpos, int t)
{
    __shared__ __align__(16) float As[16][68];
    __shared__ __align__(16) float Bs[16][68];
    const int tid = threadIdx.x;
    const int lk = tid & 15, lr = tid >> 4;
    const int tc = tid & 7,  tr = tid >> 3;
    const int n0 = blockIdx.x * 64;
    const int m0 = blockIdx.y * 64;
    const bool pri = (n0 < 1024);
    float acc[8][8] = {};
    for (int k0 = 0; k0 < 1024; k0 += 16) {
#pragma unroll
        for (int i = 0; i < 16; i++) {
            int r = lr + i * 4;
            As[lk][r] = b1[(size_t)(m0 + r) * BSTRIDE + k0 + lk];
            Bs[lk][r] = pri ? W_bpri[(size_t)(n0 + r) * 1024 + k0 + lk]
                            : W_bpos[(size_t)(n0 + r - 1024) * 2048 + k0 + lk];
        }
        __syncthreads();
        mma_tile(As, Bs, tr, tc, acc);
        __syncthreads();
    }
#pragma unroll
    for (int i = 0; i < 8; i++) {
        int m = m0 + tr * 8 + i;
#pragma unroll
        for (int j = 0; j < 8; j++) {
            int n = n0 + tc * 8 + j;
            float add = pri ? b_bpri[n]
                            : g_OB[((size_t)m * T1_ + t) * 1024 + (n - 1024)];
            g_HPQ[(size_t)m * 2048 + n] = fmaxf(acc[i][j] + add, 0.0f);
        }
    }
}

// ---------------- K4: heads. Col space 512 = [prior 256 | posterior 256],
// interleaved pairs: col 2p = mu_p, col 2p+1 = h2_p.  grid (8, 4).
__global__ void __launch_bounds__(64)
k4_heads(const float* __restrict__ W_spri, const float* __restrict__ b_spri,
         const float* __restrict__ W_spos, const float* __restrict__ b_spos,
         const float* __restrict__ np, const float* __restrict__ nq,
         float* __restrict__ o_sp, float* __restrict__ o_mup, float* __restrict__ o_stp,
         float* __restrict__ o_sq, float* __restrict__ o_muq, float* __restrict__ o_stq)
{
    __shared__ __align__(16) float As[16][68];
    __shared__ __align__(16) float Bs[16][68];
    const int tid = threadIdx.x;
    const int lk = tid & 15, lr = tid >> 4;
    const int tc = tid & 7,  tr = tid >> 3;
    const int n0 = blockIdx.x * 64;               // 0..511
    const int m0 = blockIdx.y * 64;
    const int side = n0 >> 8;                      // 0 = prior, 1 = posterior
    const float* W    = side ? W_spos : W_spri;
    const float* bias = side ? b_spos : b_spri;
    const float* nz   = side ? nq : np;
    float* o_s  = side ? o_sq  : o_sp;
    float* o_mu = side ? o_muq : o_mup;
    float* o_st = side ? o_stq : o_stp;
    float acc[8][8] = {};
    for (int k0 = 0; k0 < 1024; k0 += 16) {
#pragma unroll
        for (int i = 0; i < 16; i++) {
            int r = lr + i * 4;
            As[lk][r] = g_HPQ[(m0 + r) * 2048 + side * 1024 + k0 + lk];
            int cc  = (n0 + r) & 255;              // within-side column
            int row = (cc >> 1) + (cc & 1) * 128;  // mu rows [0,128), h2 rows [128,256)
            Bs[lk][r] = W[row * 1024 + k0 + lk];
        }
        __syncthreads();
        mma_tile(As, Bs, tr, tc, acc);
        __syncthreads();
    }
#pragma unroll
    for (int i = 0; i < 8; i++) {
        int m = m0 + tr * 8 + i;
#pragma unroll
        for (int j = 0; j < 8; j += 2) {
            int cc = (n0 + tc * 8 + j) & 255;
            int p  = cc >> 1;
            float mu = acc[i][j]     + bias[p];
            float h2 = acc[i][j + 1] + bias[p + 128];
            float sd = ((h2 > 20.0f) ? h2 : log1pf(expf(h2))) + 0.1f;  // softplus + MIN_STD
            float ep = nz[(size_t)m * SSTRIDE + p];
            size_t o = (size_t)m * SSTRIDE + p;
            o_mu[o] = mu;
            o_st[o] = sd;
            o_s [o] = mu + sd * ep;
        }
    }
}

// ---------------- host: capture-safe launch sequence -------------------------
extern "C" void kernel_launch(void* const* d_in, const int* in_sizes, int n_in,
                              void* d_out, int out_size)
{
    (void)in_sizes; (void)n_in; (void)out_size;
    const float* s0     = (const float*)d_in[0];
    const float* b0     = (const float*)d_in[1];
    const float* Act    = (const float*)d_in[2];
    const float* Obs    = (const float*)d_in[3];
    const float* np     = (const float*)d_in[4];
    const float* nq     = (const float*)d_in[5];
    const float* W_sa   = (const float*)d_in[6];
    const float* b_sa   = (const float*)d_in[7];
    const float* W_ih   = (const float*)d_in[8];
    const float* W_hh   = (const float*)d_in[9];
    const float* b_ih   = (const float*)d_in[10];
    const float* b_hh   = (const float*)d_in[11];
    const float* W_bpri = (const float*)d_in[12];
    const float* b_bpri = (const float*)d_in[13];
    const float* W_spri = (const float*)d_in[14];
    const float* b_spri = (const float*)d_in[15];
    const float* W_bpos = (const float*)d_in[16];
    const float* b_bpos = (const float*)d_in[17];
    const float* W_spos = (const float*)d_in[18];
    const float* b_spos = (const float*)d_in[19];

    float* out   = (float*)d_out;
    float* O_b   = out;                    // (B,T1,H)
    float* O_sp  = O_b   + O_B_SZ;         // (B,T1,S) x6
    float* O_mup = O_sp  + O_S_SZ;
    float* O_stp = O_mup + O_S_SZ;
    float* O_sq  = O_stp + O_S_SZ;
    float* O_muq = O_sq  + O_S_SZ;
    float* O_stq = O_muq + O_S_SZ;

    // Hoisted observation projection (independent of recurrence)
    ob_gemm<<<dim3(16, 512), 64>>>(Obs, W_bpos, b_bpos);

    for (int t = 0; t < T1_; t++) {
        const float* sprev = t ? (O_sq + (size_t)(t - 1) * S_) : s0;
        const int    ss    = t ? SSTRIDE : S_;
        const float* bprev = t ? (O_b + (size_t)(t - 1) * H_) : b0;
        const int    bs    = t ? BSTRIDE : H_;

        k1_x   <<<dim3(16, 4), 64>>>(sprev, ss, Act + (size_t)t * A_, T1_ * A_, W_sa, b_sa);
        k2_gemm<<<dim3(96, 4), 64>>>(bprev, bs, W_ih, W_hh, b_ih, b_hh);
        k2_gates<<<1024, 256>>>(bprev, bs, O_b + (size_t)t * H_);
        k3_gemm<<<dim3(32, 4), 64>>>(O_b + (size_t)t * H_, W_bpri, b_bpri, W_bpos, t);
        k4_heads<<<dim3(8, 4), 64>>>(W_spri, b_spri, W_spos, b_spos,
                                     np + (size_t)t * S_, nq + (size_t)t * S_,
                                     O_sp  + (size_t)t * S_, O_mup + (size_t)t * S_,
                                     O_stp + (size_t)t * S_, O_sq  + (size_t)t * S_,
                                     O_muq + (size_t)t * S_, O_stq + (size_t)t * S_);
    }
}

// round 14
// speedup vs baseline: 1.5558x; 1.5430x over previous
#include <cuda_runtime.h>
#include <math.h>

// Problem dims
#define B_   256
#define T1_  128
#define S_   128
#define A_   32
#define H_   1024
#define E_   1024

// Output layout (floats), tuple order: b1, s_p, mu_p, std_p, s_q, mu_q, std_q
#define O_B_SZ   (B_ * T1_ * H_)
#define O_S_SZ   (B_ * T1_ * S_)
#define SSTRIDE  (T1_ * S_)               // 16384
#define BSTRIDE  (T1_ * H_)               // 131072

// ---------------- scratch (static device memory; no allocations) ------------
__device__ float g_OB [B_ * T1_ * H_];    // precomputed o @ W_bpos_o^T + b_bpos
__device__ float g_x  [B_ * H_];          // x = relu([s,a] @ W_sa^T + b_sa)
__device__ float g_G  [B_ * 6 * H_];      // [gi (3H) | gh (3H)]
__device__ float g_HPQ[B_ * 2 * H_];      // [hp (H) | hq (H)]

// ---------------- packed f32x2 helpers (FFMA2 path, sm_103a) ----------------
__device__ __forceinline__ unsigned long long pk2(float x) {
    unsigned long long r; unsigned xi = __float_as_uint(x);
    asm("mov.b64 %0, {%1, %1};" : "=l"(r) : "r"(xi));
    return r;
}
__device__ __forceinline__ void fma2(unsigned long long& d,
                                     unsigned long long a, unsigned long long b) {
    asm("fma.rn.f32x2 %0, %1, %2, %3;" : "=l"(d) : "l"(a), "l"(b), "l"(d));
}
__device__ __forceinline__ float accf(unsigned long long v, int h) {
    return __uint_as_float(h ? (unsigned)(v >> 32) : (unsigned)v);
}

// 64x64 tile, 128 threads. Per-thread: 8 rows (as 4 packed row-pairs) x 4 cols.
// acc[p][j] = packed rows (tr*8+2p, tr*8+2p+1), col tc*4+j.
__device__ __forceinline__ void mma16(const float (*As)[68], const float (*Bs)[68],
                                      int tr, int tc, unsigned long long (&acc)[4][4])
{
#pragma unroll
    for (int k = 0; k < 16; k++) {
        const ulonglong2* ap = reinterpret_cast<const ulonglong2*>(&As[k][tr * 8]);
        ulonglong2 a0 = ap[0], a1 = ap[1];
        unsigned long long av[4] = {a0.x, a0.y, a1.x, a1.y};
        float4 bq = *reinterpret_cast<const float4*>(&Bs[k][tc * 4]);
        unsigned long long bv[4] = {pk2(bq.x), pk2(bq.y), pk2(bq.z), pk2(bq.w)};
#pragma unroll
        for (int p = 0; p < 4; p++)
#pragma unroll
            for (int j = 0; j < 4; j++)
                fma2(acc[p][j], av[p], bv[j]);
    }
}

// Double-buffered pipeline skeleton. LOADA/LOADB are expressions in (r, kk).
#define GEMM_BODY(KTOT, LOADA, LOADB)                                          \
    __shared__ __align__(16) float As[2][16][68];                              \
    __shared__ __align__(16) float Bs[2][16][68];                              \
    const int tid = threadIdx.x;                                               \
    const int lk = tid & 15, lr = tid >> 4;                                    \
    const int tc = tid & 15, tr = tid >> 4;                                    \
    unsigned long long acc[4][4] = {};                                         \
    float ra[8], rb[8];                                                        \
    {                                                                          \
        const int kk = lk;                                                     \
        _Pragma("unroll") for (int i = 0; i < 8; i++) {                        \
            const int r = lr + 8 * i;                                          \
            ra[i] = (LOADA); rb[i] = (LOADB);                                  \
        }                                                                      \
    }                                                                          \
    _Pragma("unroll") for (int i = 0; i < 8; i++) {                            \
        As[0][lk][lr + 8 * i] = ra[i]; Bs[0][lk][lr + 8 * i] = rb[i];          \
    }                                                                          \
    __syncthreads();                                                           \
    const int NK = (KTOT) / 16;                                                \
    for (int c = 0; c < NK; c++) {                                             \
        const int sb = c & 1;                                                  \
        if (c + 1 < NK) {                                                      \
            const int kk = (c + 1) * 16 + lk;                                  \
            _Pragma("unroll") for (int i = 0; i < 8; i++) {                    \
                const int r = lr + 8 * i;                                      \
                ra[i] = (LOADA); rb[i] = (LOADB);                              \
            }                                                                  \
        }                                                                      \
        mma16(As[sb], Bs[sb], tr, tc, acc);                                    \
        if (c + 1 < NK) {                                                      \
            _Pragma("unroll") for (int i = 0; i < 8; i++) {                    \
                As[sb ^ 1][lk][lr + 8 * i] = ra[i];                            \
                Bs[sb ^ 1][lk][lr + 8 * i] = rb[i];                            \
            }                                                                  \
        }                                                                      \
        __syncthreads();                                                       \
    }

// ---------------- precompute: OB = Obs @ W_bpos[:,1024:2048]^T + b_bpos ------
// M=32768, N=1024, K=1024.  grid (16, 512), 128 threads.
__global__ void __launch_bounds__(128)
ob_gemm(const float* __restrict__ Obs, const float* __restrict__ W_bpos,
        const float* __restrict__ b_bpos)
{
    const int n0 = blockIdx.x * 64;
    const int m0 = blockIdx.y * 64;
    GEMM_BODY(1024,
              Obs[(size_t)(m0 + r) * 1024 + kk],
              W_bpos[(size_t)(n0 + r) * 2048 + 1024 + kk])
#pragma unroll
    for (int p = 0; p < 4; p++)
#pragma unroll
        for (int h = 0; h < 2; h++) {
            int m = m0 + tr * 8 + 2 * p + h;
#pragma unroll
            for (int j = 0; j < 4; j++) {
                int n = n0 + tc * 4 + j;
                g_OB[(size_t)m * 1024 + n] = accf(acc[p][j], h) + b_bpos[n];
            }
        }
}

// ---------------- K1: x = relu([s,a] @ W_sa^T + b_sa) ------------------------
// M=256, N=1024, K=160.  grid (16, 4), 128 threads.
__global__ void __launch_bounds__(128)
k1_x(const float* __restrict__ s, int ss,
     const float* __restrict__ a, int sa,
     const float* __restrict__ W_sa, const float* __restrict__ b_sa)
{
    const int n0 = blockIdx.x * 64;
    const int m0 = blockIdx.y * 64;
    GEMM_BODY(160,
              (kk < 128) ? s[(size_t)(m0 + r) * ss + kk]
                         : a[(size_t)(m0 + r) * sa + (kk - 128)],
              W_sa[(n0 + r) * 160 + kk])
#pragma unroll
    for (int p = 0; p < 4; p++)
#pragma unroll
        for (int h = 0; h < 2; h++) {
            int m = m0 + tr * 8 + 2 * p + h;
#pragma unroll
            for (int j = 0; j < 4; j++) {
                int n = n0 + tc * 4 + j;
                g_x[m * 1024 + n] = fmaxf(accf(acc[p][j], h) + b_sa[n], 0.0f);
            }
        }
}

// ---------------- K2: G = [x @ W_ih^T + b_ih | bprev @ W_hh^T + b_hh] -------
// Column space 6144; cols < 3072 use A=x, else A=bprev.  grid (96, 4).
__global__ void __launch_bounds__(128)
k2_gemm(const float* __restrict__ bprev, int bs,
        const float* __restrict__ W_ih, const float* __restrict__ W_hh,
        const float* __restrict__ b_ih, const float* __restrict__ b_hh)
{
    const int n0 = blockIdx.x * 64;
    const int m0 = blockIdx.y * 64;
    const bool isX = (n0 < 3072);
    const float* W    = isX ? W_ih : W_hh;
    const float* bias = isX ? b_ih : b_hh;
    const int wn0 = isX ? n0 : (n0 - 3072);
    GEMM_BODY(1024,
              isX ? g_x[(m0 + r) * 1024 + kk]
                  : bprev[(size_t)(m0 + r) * bs + kk],
              W[(size_t)(wn0 + r) * 1024 + kk])
#pragma unroll
    for (int p = 0; p < 4; p++)
#pragma unroll
        for (int h = 0; h < 2; h++) {
            int m = m0 + tr * 8 + 2 * p + h;
#pragma unroll
            for (int j = 0; j < 4; j++) {
                int n = n0 + tc * 4 + j;
                g_G[(size_t)m * 6144 + n] = accf(acc[p][j], h) + bias[wn0 + tc * 4 + j];
            }
        }
}

// ---------------- K2b: fused GRU gates -> b1 = Beliefs[:,t,:] ---------------
__global__ void k2_gates(const float* __restrict__ bprev, int bs,
                         float* __restrict__ bout)
{
    int idx = blockIdx.x * 256 + threadIdx.x;   // < 256*1024
    int m = idx >> 10, n = idx & 1023;
    const float* g = g_G + (size_t)m * 6144;
    float ir = g[n],          iz = g[n + 1024],        in_ = g[n + 2048];
    float hr = g[3072 + n],   hz = g[3072 + 1024 + n], hn  = g[3072 + 2048 + n];
    float r  = 1.0f / (1.0f + expf(-(ir + hr)));
    float z  = 1.0f / (1.0f + expf(-(iz + hz)));
    float nn = tanhf(in_ + r * hn);
    float h  = bprev[(size_t)m * bs + n];
    bout[(size_t)m * BSTRIDE + n] = (1.0f - z) * nn + z * h;
}

// ---------------- K3: HPQ = [relu(b1@W_bpri^T+b_bpri) | relu(b1@W_bpos_b^T+OB)]
// N=2048, K=1024.  grid (32, 4).
__global__ void __launch_bounds__(128)
k3_gemm(const float* __restrict__ b1, const float* __restrict__ W_bpri,
        const float* __restrict__ b_bpri, const float* __restrict__ W_bpos, int t)
{
    const int n0 = blockIdx.x * 64;
    const int m0 = blockIdx.y * 64;
    const bool pri = (n0 < 1024);
    GEMM_BODY(1024,
              b1[(size_t)(m0 + r) * BSTRIDE + kk],
              pri ? W_bpri[(size_t)(n0 + r) * 1024 + kk]
                  : W_bpos[(size_t)(n0 + r - 1024) * 2048 + kk])
#pragma unroll
    for (int p = 0; p < 4; p++)
#pragma unroll
        for (int h = 0; h < 2; h++) {
            int m = m0 + tr * 8 + 2 * p + h;
#pragma unroll
            for (int j = 0; j < 4; j++) {
                int n = n0 + tc * 4 + j;
                float add = pri ? b_bpri[n]
                                : g_OB[((size_t)m * T1_ + t) * 1024 + (n - 1024)];
                g_HPQ[(size_t)m * 2048 + n] = fmaxf(accf(acc[p][j], h) + add, 0.0f);
            }
        }
}

// ---------------- K4: heads. Col space 512 = [prior 256 | posterior 256],
// interleaved pairs: col 2p = mu, col 2p+1 = pre-softplus.  grid (8, 4).
__global__ void __launch_bounds__(128)
k4_heads(const float* __restrict__ W_spri, const float* __restrict__ b_spri,
         const float* __restrict__ W_spos, const float* __restrict__ b_spos,
         const float* __restrict__ np, const float* __restrict__ nq,
         float* __restrict__ o_sp, float* __restrict__ o_mup, float* __restrict__ o_stp,
         float* __restrict__ o_sq, float* __restrict__ o_muq, float* __restrict__ o_stq)
{
    const int n0 = blockIdx.x * 64;               // 0..511
    const int m0 = blockIdx.y * 64;
    const int side = n0 >> 8;                      // 0 = prior, 1 = posterior
    const float* W    = side ? W_spos : W_spri;
    const float* bias = side ? b_spos : b_spri;
    const float* nz   = side ? nq : np;
    float* o_s  = side ? o_sq  : o_sp;
    float* o_mu = side ? o_muq : o_mup;
    float* o_st = side ? o_stq : o_stp;
    GEMM_BODY(1024,
              g_HPQ[(m0 + r) * 2048 + side * 1024 + kk],
              W[((((n0 + r) & 255) >> 1) + ((n0 + r) & 1) * 128) * 1024 + kk])
#pragma unroll
    for (int p = 0; p < 4; p++)
#pragma unroll
        for (int h = 0; h < 2; h++) {
            int m = m0 + tr * 8 + 2 * p + h;
#pragma unroll
            for (int j = 0; j < 4; j += 2) {
                int cc = (n0 + tc * 4 + j) & 255;
                int pp = cc >> 1;
                float mu = accf(acc[p][j],     h) + bias[pp];
                float h2 = accf(acc[p][j + 1], h) + bias[pp + 128];
                float sd = ((h2 > 20.0f) ? h2 : log1pf(expf(h2))) + 0.1f; // softplus+MIN_STD
                float ep = nz[(size_t)m * SSTRIDE + pp];
                size_t o = (size_t)m * SSTRIDE + pp;
                o_mu[o] = mu;
                o_st[o] = sd;
                o_s [o] = mu + sd * ep;
            }
        }
}

// ---------------- host: capture-safe launch sequence -------------------------
extern "C" void kernel_launch(void* const* d_in, const int* in_sizes, int n_in,
                              void* d_out, int out_size)
{
    (void)in_sizes; (void)n_in; (void)out_size;
    const float* s0     = (const float*)d_in[0];
    const float* b0     = (const float*)d_in[1];
    const float* Act    = (const float*)d_in[2];
    const float* Obs    = (const float*)d_in[3];
    const float* np     = (const float*)d_in[4];
    const float* nq     = (const float*)d_in[5];
    const float* W_sa   = (const float*)d_in[6];
    const float* b_sa   = (const float*)d_in[7];
    const float* W_ih   = (const float*)d_in[8];
    const float* W_hh   = (const float*)d_in[9];
    const float* b_ih   = (const float*)d_in[10];
    const float* b_hh   = (const float*)d_in[11];
    const float* W_bpri = (const float*)d_in[12];
    const float* b_bpri = (const float*)d_in[13];
    const float* W_spri = (const float*)d_in[14];
    const float* b_spri = (const float*)d_in[15];
    const float* W_bpos = (const float*)d_in[16];
    const float* b_bpos = (const float*)d_in[17];
    const float* W_spos = (const float*)d_in[18];
    const float* b_spos = (const float*)d_in[19];

    float* out   = (float*)d_out;
    float* O_b   = out;                    // (B,T1,H)
    float* O_sp  = O_b   + O_B_SZ;         // (B,T1,S) x6
    float* O_mup = O_sp  + O_S_SZ;
    float* O_stp = O_mup + O_S_SZ;
    float* O_sq  = O_stp + O_S_SZ;
    float* O_muq = O_sq  + O_S_SZ;
    float* O_stq = O_muq + O_S_SZ;

    // Hoisted observation projection (independent of recurrence)
    ob_gemm<<<dim3(16, 512), 128>>>(Obs, W_bpos, b_bpos);

    for (int t = 0; t < T1_; t++) {
        const float* sprev = t ? (O_sq + (size_t)(t - 1) * S_) : s0;
        const int    ss    = t ? SSTRIDE : S_;
        const float* bprev = t ? (O_b + (size_t)(t - 1) * H_) : b0;
        const int    bs    = t ? BSTRIDE : H_;

        k1_x   <<<dim3(16, 4), 128>>>(sprev, ss, Act + (size_t)t * A_, T1_ * A_, W_sa, b_sa);
        k2_gemm<<<dim3(96, 4), 128>>>(bprev, bs, W_ih, W_hh, b_ih, b_hh);
        k2_gates<<<1024, 256>>>(bprev, bs, O_b + (size_t)t * H_);
        k3_gemm<<<dim3(32, 4), 128>>>(O_b + (size_t)t * H_, W_bpri, b_bpri, W_bpos, t);
        k4_heads<<<dim3(8, 4), 128>>>(W_spri, b_spri, W_spos, b_spos,
                                      np + (size_t)t * S_, nq + (size_t)t * S_,
                                      O_sp  + (size_t)t * S_, O_mup + (size_t)t * S_,
                                      O_stp + (size_t)t * S_, O_sq  + (size_t)t * S_,
                                      O_muq + (size_t)t * S_, O_stq + (size_t)t * S_);
    }
}

// round 15
// speedup vs baseline: 1.5603x; 1.0029x over previous
#include <cuda_runtime.h>
#include <math.h>

// Problem dims
#define B_   256
#define T1_  128
#define S_   128
#define A_   32
#define H_   1024
#define E_   1024

// Output layout (floats), tuple order: b1, s_p, mu_p, std_p, s_q, mu_q, std_q
#define O_B_SZ   (B_ * T1_ * H_)
#define O_S_SZ   (B_ * T1_ * S_)
#define SSTRIDE  (T1_ * S_)               // 16384
#define BSTRIDE  (T1_ * H_)               // 131072

// ---------------- scratch (static device memory; no allocations) ------------
__device__ float g_OB [B_ * T1_ * H_];    // precomputed o @ W_bpos_o^T + b_bpos
__device__ float g_x  [B_ * H_];          // x = relu([s,a] @ W_sa^T + b_sa)
__device__ float g_G  [B_ * 6 * H_];      // [gi (3H) | gh (3H)]
__device__ float g_HPQ[B_ * 2 * H_];      // [hp (H) | hq (H)]

// ---------------- packed f32x2 helpers (FFMA2 path, sm_103a) ----------------
__device__ __forceinline__ unsigned long long pk2(float x) {
    unsigned long long r; unsigned xi = __float_as_uint(x);
    asm("mov.b64 %0, {%1, %1};" : "=l"(r) : "r"(xi));
    return r;
}
__device__ __forceinline__ void fma2(unsigned long long& d,
                                     unsigned long long a, unsigned long long b) {
    asm("fma.rn.f32x2 %0, %1, %2, %3;" : "=l"(d) : "l"(a), "l"(b), "l"(d));
}
__device__ __forceinline__ float accf(unsigned long long v, int h) {
    return __uint_as_float(h ? (unsigned)(v >> 32) : (unsigned)v);
}

// 64x64 tile, 128 threads. Per-thread: 8 rows (as 4 packed row-pairs) x 4 cols.
// acc[p][j] = packed rows (tr*8+2p, tr*8+2p+1), col tc*4+j.
__device__ __forceinline__ void mma16(const float (*As)[68], const float (*Bs)[68],
                                      int tr, int tc, unsigned long long (&acc)[4][4])
{
#pragma unroll
    for (int k = 0; k < 16; k++) {
        const ulonglong2* ap = reinterpret_cast<const ulonglong2*>(&As[k][tr * 8]);
        ulonglong2 a0 = ap[0], a1 = ap[1];
        unsigned long long av[4] = {a0.x, a0.y, a1.x, a1.y};
        float4 bq = *reinterpret_cast<const float4*>(&Bs[k][tc * 4]);
        unsigned long long bv[4] = {pk2(bq.x), pk2(bq.y), pk2(bq.z), pk2(bq.w)};
#pragma unroll
        for (int p = 0; p < 4; p++)
#pragma unroll
            for (int j = 0; j < 4; j++)
                fma2(acc[p][j], av[p], bv[j]);
    }
}

// Double-buffered pipeline skeleton. LOADA/LOADB are expressions in (r, kk).
#define GEMM_BODY(KTOT, LOADA, LOADB)                                          \
    __shared__ __align__(16) float As[2][16][68];                              \
    __shared__ __align__(16) float Bs[2][16][68];                              \
    const int tid = threadIdx.x;                                               \
    const int lk = tid & 15, lr = tid >> 4;                                    \
    const int tc = tid & 15, tr = tid >> 4;                                    \
    unsigned long long acc[4][4] = {};                                         \
    float ra[8], rb[8];                                                        \
    {                                                                          \
        const int kk = lk;                                                     \
        _Pragma("unroll") for (int i = 0; i < 8; i++) {                        \
            const int r = lr + 8 * i;                                          \
            ra[i] = (LOADA); rb[i] = (LOADB);                                  \
        }                                                                      \
    }                                                                          \
    _Pragma("unroll") for (int i = 0; i < 8; i++) {                            \
        As[0][lk][lr + 8 * i] = ra[i]; Bs[0][lk][lr + 8 * i] = rb[i];          \
    }                                                                          \
    __syncthreads();                                                           \
    const int NK = (KTOT) / 16;                                                \
    for (int c = 0; c < NK; c++) {                                             \
        const int sb = c & 1;                                                  \
        if (c + 1 < NK) {                                                      \
            const int kk = (c + 1) * 16 + lk;                                  \
            _Pragma("unroll") for (int i = 0; i < 8; i++) {                    \
                const int r = lr + 8 * i;                                      \
                ra[i] = (LOADA); rb[i] = (LOADB);                              \
            }                                                                  \
        }                                                                      \
        mma16(As[sb], Bs[sb], tr, tc, acc);                                    \
        if (c + 1 < NK) {                                                      \
            _Pragma("unroll") for (int i = 0; i < 8; i++) {                    \
                As[sb ^ 1][lk][lr + 8 * i] = ra[i];                            \
                Bs[sb ^ 1][lk][lr + 8 * i] = rb[i];                            \
            }                                                                  \
        }                                                                      \
        __syncthreads();                                                       \
    }

// ---------------- precompute: OB = Obs @ W_bpos[:,1024:2048]^T + b_bpos ------
// M=32768, N=1024, K=1024.  grid (16, 512), 128 threads.
__global__ void __launch_bounds__(128)
ob_gemm(const float* __restrict__ Obs, const float* __restrict__ W_bpos,
        const float* __restrict__ b_bpos)
{
    const int n0 = blockIdx.x * 64;
    const int m0 = blockIdx.y * 64;
    GEMM_BODY(1024,
              Obs[(size_t)(m0 + r) * 1024 + kk],
              W_bpos[(size_t)(n0 + r) * 2048 + 1024 + kk])
#pragma unroll
    for (int p = 0; p < 4; p++)
#pragma unroll
        for (int h = 0; h < 2; h++) {
            int m = m0 + tr * 8 + 2 * p + h;
#pragma unroll
            for (int j = 0; j < 4; j++) {
                int n = n0 + tc * 4 + j;
                g_OB[(size_t)m * 1024 + n] = accf(acc[p][j], h) + b_bpos[n];
            }
        }
}

// ---------------- K1: x = relu([s,a] @ W_sa^T + b_sa) ------------------------
// M=256, N=1024, K=160.  grid (16, 4), 128 threads.
__global__ void __launch_bounds__(128)
k1_x(const float* __restrict__ s, int ss,
     const float* __restrict__ a, int sa,
     const float* __restrict__ W_sa, const float* __restrict__ b_sa)
{
    const int n0 = blockIdx.x * 64;
    const int m0 = blockIdx.y * 64;
    GEMM_BODY(160,
              (kk < 128) ? s[(size_t)(m0 + r) * ss + kk]
                         : a[(size_t)(m0 + r) * sa + (kk - 128)],
              W_sa[(n0 + r) * 160 + kk])
#pragma unroll
    for (int p = 0; p < 4; p++)
#pragma unroll
        for (int h = 0; h < 2; h++) {
            int m = m0 + tr * 8 + 2 * p + h;
#pragma unroll
            for (int j = 0; j < 4; j++) {
                int n = n0 + tc * 4 + j;
                g_x[m * 1024 + n] = fmaxf(accf(acc[p][j], h) + b_sa[n], 0.0f);
            }
        }
}

// ---------------- K2: G = [x @ W_ih^T + b_ih | bprev @ W_hh^T + b_hh] -------
// Column space 6144; cols < 3072 use A=x, else A=bprev.  grid (96, 4).
__global__ void __launch_bounds__(128)
k2_gemm(const float* __restrict__ bprev, int bs,
        const float* __restrict__ W_ih, const float* __restrict__ W_hh,
        const float* __restrict__ b_ih, const float* __restrict__ b_hh)
{
    const int n0 = blockIdx.x * 64;
    const int m0 = blockIdx.y * 64;
    const bool isX = (n0 < 3072);
    const float* W    = isX ? W_ih : W_hh;
    const float* bias = isX ? b_ih : b_hh;
    const int wn0 = isX ? n0 : (n0 - 3072);
    GEMM_BODY(1024,
              isX ? g_x[(m0 + r) * 1024 + kk]
                  : bprev[(size_t)(m0 + r) * bs + kk],
              W[(size_t)(wn0 + r) * 1024 + kk])
#pragma unroll
    for (int p = 0; p < 4; p++)
#pragma unroll
        for (int h = 0; h < 2; h++) {
            int m = m0 + tr * 8 + 2 * p + h;
#pragma unroll
            for (int j = 0; j < 4; j++) {
                int n = n0 + tc * 4 + j;
                g_G[(size_t)m * 6144 + n] = accf(acc[p][j], h) + bias[wn0 + tc * 4 + j];
            }
        }
}

// ---------------- K2b: fused GRU gates -> b1 = Beliefs[:,t,:] ---------------
__global__ void k2_gates(const float* __restrict__ bprev, int bs,
                         float* __restrict__ bout)
{
    int idx = blockIdx.x * 256 + threadIdx.x;   // < 256*1024
    int m = idx >> 10, n = idx & 1023;
    const float* g = g_G + (size_t)m * 6144;
    float ir = g[n],          iz = g[n + 1024],        in_ = g[n + 2048];
    float hr = g[3072 + n],   hz = g[3072 + 1024 + n], hn  = g[3072 + 2048 + n];
    float r  = 1.0f / (1.0f + expf(-(ir + hr)));
    float z  = 1.0f / (1.0f + expf(-(iz + hz)));
    float nn = tanhf(in_ + r * hn);
    float h  = bprev[(size_t)m * bs + n];
    bout[(size_t)m * BSTRIDE + n] = (1.0f - z) * nn + z * h;
}

// ---------------- K3: HPQ = [relu(b1@W_bpri^T+b_bpri) | relu(b1@W_bpos_b^T+OB)]
// N=2048, K=1024.  grid (32, 4).
__global__ void __launch_bounds__(128)
k3_gemm(const float* __restrict__ b1, const float* __restrict__ W_bpri,
        const float* __restrict__ b_bpri, const float* __restrict__ W_bpos, int t)
{
    const int n0 = blockIdx.x * 64;
    const int m0 = blockIdx.y * 64;
    const bool pri = (n0 < 1024);
    GEMM_BODY(1024,
              b1[(size_t)(m0 + r) * BSTRIDE + kk],
              pri ? W_bpri[(size_t)(n0 + r) * 1024 + kk]
                  : W_bpos[(size_t)(n0 + r - 1024) * 2048 + kk])
#pragma unroll
    for (int p = 0; p < 4; p++)
#pragma unroll
        for (int h = 0; h < 2; h++) {
            int m = m0 + tr * 8 + 2 * p + h;
#pragma unroll
            for (int j = 0; j < 4; j++) {
                int n = n0 + tc * 4 + j;
                float add = pri ? b_bpri[n]
                                : g_OB[((size_t)m * T1_ + t) * 1024 + (n - 1024)];
                g_HPQ[(size_t)m * 2048 + n] = fmaxf(accf(acc[p][j], h) + add, 0.0f);
            }
        }
}

// ---------------- K4: heads. Col space 512 = [prior 256 | posterior 256],
// interleaved pairs: col 2p = mu, col 2p+1 = pre-softplus.  grid (8, 4).
__global__ void __launch_bounds__(128)
k4_heads(const float* __restrict__ W_spri, const float* __restrict__ b_spri,
         const float* __restrict__ W_spos, const float* __restrict__ b_spos,
         const float* __restrict__ np, const float* __restrict__ nq,
         float* __restrict__ o_sp, float* __restrict__ o_mup, float* __restrict__ o_stp,
         float* __restrict__ o_sq, float* __restrict__ o_muq, float* __restrict__ o_stq)
{
    const int n0 = blockIdx.x * 64;               // 0..511
    const int m0 = blockIdx.y * 64;
    const int side = n0 >> 8;                      // 0 = prior, 1 = posterior
    const float* W    = side ? W_spos : W_spri;
    const float* bias = side ? b_spos : b_spri;
    const float* nz   = side ? nq : np;
    float* o_s  = side ? o_sq  : o_sp;
    float* o_mu = side ? o_muq : o_mup;
    float* o_st = side ? o_stq : o_stp;
    GEMM_BODY(1024,
              g_HPQ[(m0 + r) * 2048 + side * 1024 + kk],
              W[((((n0 + r) & 255) >> 1) + ((n0 + r) & 1) * 128) * 1024 + kk])
#pragma unroll
    for (int p = 0; p < 4; p++)
#pragma unroll
        for (int h = 0; h < 2; h++) {
            int m = m0 + tr * 8 + 2 * p + h;
#pragma unroll
            for (int j = 0; j < 4; j += 2) {
                int cc = (n0 + tc * 4 + j) & 255;
                int pp = cc >> 1;
                float mu = accf(acc[p][j],     h) + bias[pp];
                float h2 = accf(acc[p][j + 1], h) + bias[pp + 128];
                float sd = ((h2 > 20.0f) ? h2 : log1pf(expf(h2))) + 0.1f; // softplus+MIN_STD
                float ep = nz[(size_t)m * SSTRIDE + pp];
                size_t o = (size_t)m * SSTRIDE + pp;
                o_mu[o] = mu;
                o_st[o] = sd;
                o_s [o] = mu + sd * ep;
            }
        }
}

// ---------------- host: capture-safe launch sequence -------------------------
extern "C" void kernel_launch(void* const* d_in, const int* in_sizes, int n_in,
                              void* d_out, int out_size)
{
    (void)in_sizes; (void)n_in; (void)out_size;
    const float* s0     = (const float*)d_in[0];
    const float* b0     = (const float*)d_in[1];
    const float* Act    = (const float*)d_in[2];
    const float* Obs    = (const float*)d_in[3];
    const float* np     = (const float*)d_in[4];
    const float* nq     = (const float*)d_in[5];
    const float* W_sa   = (const float*)d_in[6];
    const float* b_sa   = (const float*)d_in[7];
    const float* W_ih   = (const float*)d_in[8];
    const float* W_hh   = (const float*)d_in[9];
    const float* b_ih   = (const float*)d_in[10];
    const float* b_hh   = (const float*)d_in[11];
    const float* W_bpri = (const float*)d_in[12];
    const float* b_bpri = (const float*)d_in[13];
    const float* W_spri = (const float*)d_in[14];
    const float* b_spri = (const float*)d_in[15];
    const float* W_bpos = (const float*)d_in[16];
    const float* b_bpos = (const float*)d_in[17];
    const float* W_spos = (const float*)d_in[18];
    const float* b_spos = (const float*)d_in[19];

    float* out   = (float*)d_out;
    float* O_b   = out;                    // (B,T1,H)
    float* O_sp  = O_b   + O_B_SZ;         // (B,T1,S) x6
    float* O_mup = O_sp  + O_S_SZ;
    float* O_stp = O_mup + O_S_SZ;
    float* O_sq  = O_stp + O_S_SZ;
    float* O_muq = O_sq  + O_S_SZ;
    float* O_stq = O_muq + O_S_SZ;

    // Hoisted observation projection (independent of recurrence)
    ob_gemm<<<dim3(16, 512), 128>>>(Obs, W_bpos, b_bpos);

    for (int t = 0; t < T1_; t++) {
        const float* sprev = t ? (O_sq + (size_t)(t - 1) * S_) : s0;
        const int    ss    = t ? SSTRIDE : S_;
        const float* bprev = t ? (O_b + (size_t)(t - 1) * H_) : b0;
        const int    bs    = t ? BSTRIDE : H_;

        k1_x   <<<dim3(16, 4), 128>>>(sprev, ss, Act + (size_t)t * A_, T1_ * A_, W_sa, b_sa);
        k2_gemm<<<dim3(96, 4), 128>>>(bprev, bs, W_ih, W_hh, b_ih, b_hh);
        k2_gates<<<1024, 256>>>(bprev, bs, O_b + (size_t)t * H_);
        k3_gemm<<<dim3(32, 4), 128>>>(O_b + (size_t)t * H_, W_bpri, b_bpri, W_bpos, t);
        k4_heads<<<dim3(8, 4), 128>>>(W_spri, b_spri, W_spos, b_spos,
                                      np + (size_t)t * S_, nq + (size_t)t * S_,
                                      O_sp  + (size_t)t * S_, O_mup + (size_t)t * S_,
                                      O_stp + (size_t)t * S_, O_sq  + (size_t)t * S_,
                                      O_muq + (size_t)t * S_, O_stq + (size_t)t * S_);
    }
}